// round 5
// baseline (speedup 1.0000x reference)
#include <cuda_runtime.h>
#include <cuda_fp16.h>
#include <cstdint>

// CosSimilarity via fp16 mma.sync (legacy HMMA; tcgen05 unavailable: harness
// ptxas targets plain sm_103).
//  K1: normalize rows (x side pre-scaled by 1/TEMP=20) -> fp16 scratch.
//  K2: C = Xh @ Yh^T. BM=256, BN=128, BK=64, 4-stage cp.async pipeline
//      (192KB smem, 1 CTA/SM), 8 warps (4x2), warp tile 64x64 -> 128 B of
//      smem reads per HMMA (vs 192 in R4), m16n8k16, fp32 accum.

#define NROWS 4096
#define DDIM  1024
#define BM 256
#define BN 128
#define BK 64
#define NSTAGE 4
#define KITERS (DDIM / BK)              // 16
#define STAGE_BYTES ((BM + BN) * 128)   // 48 KB
#define SMEM_DYN (NSTAGE * STAGE_BYTES) // 192 KB

__device__ __align__(1024) __half g_xh[NROWS * DDIM];
__device__ __align__(1024) __half g_yh[NROWS * DDIM];

__device__ __forceinline__ uint32_t smem_u32(const void* p) {
    uint32_t a;
    asm("{ .reg .u64 t; cvta.to.shared.u64 t, %1; cvt.u32.u64 %0, t; }" : "=r"(a) : "l"(p));
    return a;
}

#define CP_ASYNC16(dst, src) \
    asm volatile("cp.async.cg.shared.global [%0], [%1], 16;" :: "r"(dst), "l"(src))
#define CP_COMMIT() asm volatile("cp.async.commit_group;" ::: "memory")
#define CP_WAIT2()  asm volatile("cp.async.wait_group 2;" ::: "memory")

__device__ __forceinline__ uint32_t swz(uint32_t off) {
    return off ^ ((off >> 3) & 0x70);
}

__device__ __forceinline__ void ldsm_x4(uint32_t* r, uint32_t addr) {
    asm volatile("ldmatrix.sync.aligned.m8n8.x4.shared.b16 {%0,%1,%2,%3}, [%4];"
                 : "=r"(r[0]), "=r"(r[1]), "=r"(r[2]), "=r"(r[3]) : "r"(addr));
}

__device__ __forceinline__ void mma16816(float* c, const uint32_t* a, const uint32_t* b) {
    asm volatile(
        "mma.sync.aligned.m16n8k16.row.col.f32.f16.f16.f32 "
        "{%0,%1,%2,%3}, {%4,%5,%6,%7}, {%8,%9}, {%0,%1,%2,%3};"
        : "+f"(c[0]), "+f"(c[1]), "+f"(c[2]), "+f"(c[3])
        : "r"(a[0]), "r"(a[1]), "r"(a[2]), "r"(a[3]), "r"(b[0]), "r"(b[1]));
}

// ---------------------------------------------------------------------------
// Kernel 1: row normalization -> fp16 (one 256-thread block per row)
// ---------------------------------------------------------------------------
__global__ void norm_kernel(const float* __restrict__ x, const float* __restrict__ y) {
    int row = blockIdx.x;
    const float4* src; __half2* dst; float extra;
    if (row < NROWS) {
        src = (const float4*)(x + (size_t)row * DDIM);
        dst = (__half2*)(g_xh + (size_t)row * DDIM);
        extra = 20.0f;                  // 1/TEMP folded into x side
    } else {
        int r = row - NROWS;
        src = (const float4*)(y + (size_t)r * DDIM);
        dst = (__half2*)(g_yh + (size_t)r * DDIM);
        extra = 1.0f;
    }
    int t = threadIdx.x;
    float4 v = src[t];
    float ss = v.x * v.x + v.y * v.y + v.z * v.z + v.w * v.w;
    #pragma unroll
    for (int o = 16; o > 0; o >>= 1) ss += __shfl_xor_sync(0xffffffffu, ss, o);

    __shared__ float wss[8];
    __shared__ float sinv;
    if ((t & 31) == 0) wss[t >> 5] = ss;
    __syncthreads();
    if (t == 0) {
        float tot = 0.0f;
        #pragma unroll
        for (int i = 0; i < 8; i++) tot += wss[i];
        sinv = extra / fmaxf(sqrtf(tot), 1e-8f);
    }
    __syncthreads();
    float inv = sinv;
    dst[2 * t]     = __floats2half2_rn(v.x * inv, v.y * inv);
    dst[2 * t + 1] = __floats2half2_rn(v.z * inv, v.w * inv);
}

// ---------------------------------------------------------------------------
// Kernel 2: HMMA GEMM, warp tile 64x64
// ---------------------------------------------------------------------------
__global__ void __launch_bounds__(256) gemm_kernel(float* __restrict__ C) {
    extern __shared__ __align__(1024) char smem[];
    const uint32_t smem_base = smem_u32(smem);
    const int tid = threadIdx.x;
    const int wid = tid >> 5;
    const int lid = tid & 31;
    const int rowA0 = blockIdx.y * BM;   // x rows
    const int rowB0 = blockIdx.x * BN;   // y rows

    const int wm = wid & 3;              // m band (64 rows each)
    const int wn = wid >> 2;             // n band (64 cols each)

    // ldmatrix lane geometry
    const int g   = lid >> 3;
    const int rin = lid & 7;
    const int a_m  = (g & 1) * 8 + rin;  // row within 16-row A tile
    const int a_kb = (g >> 1) * 16;      // byte offset within k16 (0/16)
    const int b_n  = (g >> 1) * 8 + rin; // row within 16-row B tile pair
    const int b_kb = (g & 1) * 16;

    uint32_t a_rowoff[4], b_rowoff[4];
    #pragma unroll
    for (int t = 0; t < 4; t++)
        a_rowoff[t] = (uint32_t)(wm * 64 + t * 16 + a_m) * 128;
    #pragma unroll
    for (int p = 0; p < 4; p++)
        b_rowoff[p] = (uint32_t)(BM + wn * 64 + p * 16 + b_n) * 128;

    const char* agbase = (const char*)(g_xh + (size_t)rowA0 * DDIM);
    const char* bgbase = (const char*)(g_yh + (size_t)rowB0 * DDIM);

    // Stage loader: (256+128) rows x 128B = 3072 16B chunks, 12 per thread.
    auto load_stage = [&](int sbuf, int kidx) {
        uint32_t sbase = smem_base + sbuf * STAGE_BYTES;
        const char* ag = agbase + kidx * (BK * 2);
        const char* bg = bgbase + kidx * (BK * 2);
        #pragma unroll
        for (int k = 0; k < 12; k++) {
            int i = tid + k * 256;
            int c = (i & 7) * 16;
            if (i < BM * 8) {
                int r = i >> 3;                       // 0..255
                uint32_t off = swz((uint32_t)(r * 128 + c));
                CP_ASYNC16(sbase + off, ag + (size_t)r * (DDIM * 2) + c);
            } else {
                int r = (i - BM * 8) >> 3;            // 0..127
                uint32_t off = swz((uint32_t)((BM + r) * 128 + c));
                CP_ASYNC16(sbase + off, bg + (size_t)r * (DDIM * 2) + c);
            }
        }
        CP_COMMIT();
    };

    float acc[4][8][4];
    #pragma unroll
    for (int mt = 0; mt < 4; mt++)
        #pragma unroll
        for (int nt = 0; nt < 8; nt++)
            #pragma unroll
            for (int q = 0; q < 4; q++)
                acc[mt][nt][q] = 0.0f;

    // Prologue: stages 0..2
    #pragma unroll
    for (int s = 0; s < NSTAGE - 1; s++) load_stage(s, s);

    int sb = 0;             // buffer for iteration `it`
    int lb = NSTAGE - 1;    // buffer to refill
    for (int it = 0; it < KITERS; ++it) {
        CP_WAIT2();            // stage `it` resident (<=2 newer groups in flight)
        __syncthreads();       // all warps done with buffer being refilled

        int j = it + (NSTAGE - 1);
        if (j < KITERS) load_stage(lb, j);
        else            CP_COMMIT();          // keep group accounting uniform

        const uint32_t sbase = smem_base + sb * STAGE_BYTES;
        #pragma unroll
        for (int ks = 0; ks < 4; ks++) {
            const uint32_t kb = ks * 32;
            uint32_t a[4][4];
            #pragma unroll
            for (int t = 0; t < 4; t++)
                ldsm_x4(a[t], sbase + swz(a_rowoff[t] + kb + a_kb));
            uint32_t b[8][2];
            #pragma unroll
            for (int p = 0; p < 4; p++) {
                uint32_t r[4];
                ldsm_x4(r, sbase + swz(b_rowoff[p] + kb + b_kb));
                b[2 * p][0] = r[0]; b[2 * p][1] = r[1];
                b[2 * p + 1][0] = r[2]; b[2 * p + 1][1] = r[3];
            }
            #pragma unroll
            for (int mt = 0; mt < 4; mt++)
                #pragma unroll
                for (int nt = 0; nt < 8; nt++)
                    mma16816(acc[mt][nt], a[mt], b[nt]);
        }
        sb = (sb == NSTAGE - 1) ? 0 : sb + 1;
        lb = (lb == NSTAGE - 1) ? 0 : lb + 1;
    }

    // Epilogue: direct register -> gmem (float2 stores)
    const int crow = rowA0 + wm * 64 + (lid >> 2);
    const int ccol = rowB0 + wn * 64 + (lid & 3) * 2;
    #pragma unroll
    for (int mt = 0; mt < 4; mt++) {
        #pragma unroll
        for (int nt = 0; nt < 8; nt++) {
            float* p0 = C + (size_t)(crow + mt * 16) * NROWS + ccol + nt * 8;
            float* p1 = p0 + 8 * NROWS;
            *(float2*)p0 = make_float2(acc[mt][nt][0], acc[mt][nt][1]);
            *(float2*)p1 = make_float2(acc[mt][nt][2], acc[mt][nt][3]);
        }
    }
}

// ---------------------------------------------------------------------------
extern "C" void kernel_launch(void* const* d_in, const int* in_sizes, int n_in,
                              void* d_out, int out_size) {
    const float* x = (const float*)d_in[0];
    const float* y = (const float*)d_in[1];
    float* out = (float*)d_out;

    cudaFuncSetAttribute(gemm_kernel, cudaFuncAttributeMaxDynamicSharedMemorySize, SMEM_DYN);

    norm_kernel<<<2 * NROWS, 256>>>(x, y);

    dim3 grid(NROWS / BN, NROWS / BM);   // (32, 16) = 512 CTAs
    gemm_kernel<<<grid, 256, SMEM_DYN>>>(out);
}

// round 6
// speedup vs baseline: 1.2355x; 1.2355x over previous
#include <cuda_runtime.h>
#include <cuda_fp16.h>
#include <cstdint>

// CosSimilarity via fp16 mma.sync (legacy HMMA; tcgen05 unavailable: harness
// ptxas targets plain sm_103).
//  K1: normalize rows (x side pre-scaled by 1/TEMP=20) -> fp16 scratch.
//  K2: C = Xh @ Yh^T. R4 config (BM=BN=128, BK=64, 3-stage cp.async, 2 CTA/SM,
//      warp 32x64) + PERSISTENT CTAs: grid=296, each CTA streams multiple
//      tiles through one continuous cp.async pipeline (no wave tail, no
//      per-tile pipeline restart; next tile's loads overlap epilogue).

#define NROWS 4096
#define DDIM  1024
#define BM 128
#define BN 128
#define BK 64
#define NSTAGE 3
#define KITERS (DDIM / BK)              // 16
#define STAGE_BYTES ((BM + BN) * 128)   // 32 KB
#define SMEM_DYN (NSTAGE * STAGE_BYTES) // 96 KB
#define NTILES ((NROWS / BM) * (NROWS / BN))   // 1024
#define GRID_P 296                      // 2 x 148 SMs

__device__ __align__(1024) __half g_xh[NROWS * DDIM];
__device__ __align__(1024) __half g_yh[NROWS * DDIM];

__device__ __forceinline__ uint32_t smem_u32(const void* p) {
    uint32_t a;
    asm("{ .reg .u64 t; cvta.to.shared.u64 t, %1; cvt.u32.u64 %0, t; }" : "=r"(a) : "l"(p));
    return a;
}

#define CP_ASYNC16(dst, src) \
    asm volatile("cp.async.cg.shared.global [%0], [%1], 16;" :: "r"(dst), "l"(src))
#define CP_COMMIT() asm volatile("cp.async.commit_group;" ::: "memory")
#define CP_WAIT1()  asm volatile("cp.async.wait_group 1;" ::: "memory")

__device__ __forceinline__ uint32_t swz(uint32_t off) {
    return off ^ ((off >> 3) & 0x70);
}

__device__ __forceinline__ void ldsm_x4(uint32_t* r, uint32_t addr) {
    asm volatile("ldmatrix.sync.aligned.m8n8.x4.shared.b16 {%0,%1,%2,%3}, [%4];"
                 : "=r"(r[0]), "=r"(r[1]), "=r"(r[2]), "=r"(r[3]) : "r"(addr));
}

__device__ __forceinline__ void mma16816(float* c, const uint32_t* a, const uint32_t* b) {
    asm volatile(
        "mma.sync.aligned.m16n8k16.row.col.f32.f16.f16.f32 "
        "{%0,%1,%2,%3}, {%4,%5,%6,%7}, {%8,%9}, {%0,%1,%2,%3};"
        : "+f"(c[0]), "+f"(c[1]), "+f"(c[2]), "+f"(c[3])
        : "r"(a[0]), "r"(a[1]), "r"(a[2]), "r"(a[3]), "r"(b[0]), "r"(b[1]));
}

// ---------------------------------------------------------------------------
// Kernel 1: row normalization -> fp16 (one 256-thread block per row)
// ---------------------------------------------------------------------------
__global__ void norm_kernel(const float* __restrict__ x, const float* __restrict__ y) {
    int row = blockIdx.x;
    const float4* src; __half2* dst; float extra;
    if (row < NROWS) {
        src = (const float4*)(x + (size_t)row * DDIM);
        dst = (__half2*)(g_xh + (size_t)row * DDIM);
        extra = 20.0f;                  // 1/TEMP folded into x side
    } else {
        int r = row - NROWS;
        src = (const float4*)(y + (size_t)r * DDIM);
        dst = (__half2*)(g_yh + (size_t)r * DDIM);
        extra = 1.0f;
    }
    int t = threadIdx.x;
    float4 v = src[t];
    float ss = v.x * v.x + v.y * v.y + v.z * v.z + v.w * v.w;
    #pragma unroll
    for (int o = 16; o > 0; o >>= 1) ss += __shfl_xor_sync(0xffffffffu, ss, o);

    __shared__ float wss[8];
    __shared__ float sinv;
    if ((t & 31) == 0) wss[t >> 5] = ss;
    __syncthreads();
    if (t == 0) {
        float tot = 0.0f;
        #pragma unroll
        for (int i = 0; i < 8; i++) tot += wss[i];
        sinv = extra / fmaxf(sqrtf(tot), 1e-8f);
    }
    __syncthreads();
    float inv = sinv;
    dst[2 * t]     = __floats2half2_rn(v.x * inv, v.y * inv);
    dst[2 * t + 1] = __floats2half2_rn(v.z * inv, v.w * inv);
}

// ---------------------------------------------------------------------------
// Kernel 2: persistent HMMA GEMM, 2 CTAs/SM
// ---------------------------------------------------------------------------
__global__ void __launch_bounds__(256, 2) gemm_kernel(float* __restrict__ C) {
    extern __shared__ __align__(1024) char smem[];
    const uint32_t smem_base = smem_u32(smem);
    const int tid = threadIdx.x;
    const int wid = tid >> 5;
    const int lid = tid & 31;

    const int wm = wid & 3;              // m band (32 rows each)
    const int wn = wid >> 2;             // n band (64 cols each)

    // ldmatrix lane geometry
    const int g   = lid >> 3;
    const int rin = lid & 7;
    const int a_m  = (g & 1) * 8 + rin;
    const int a_kb = (g >> 1) * 16;
    const int b_n  = (g >> 1) * 8 + rin;
    const int b_kb = (g & 1) * 16;

    uint32_t a_rowoff[2], b_rowoff[4];
    #pragma unroll
    for (int t = 0; t < 2; t++)
        a_rowoff[t] = (uint32_t)(wm * 32 + t * 16 + a_m) * 128;
    #pragma unroll
    for (int p = 0; p < 4; p++)
        b_rowoff[p] = (uint32_t)(BM + wn * 64 + p * 16 + b_n) * 128;

    // Stage loader for (tile lt, k-slice lk). 2048 16B chunks, 8 per thread.
    auto load_stage = [&](int sbuf, int lt, int lk) {
        uint32_t sbase = smem_base + sbuf * STAGE_BYTES;
        const char* ag = (const char*)g_xh
            + ((size_t)(lt >> 5) * BM) * (DDIM * 2) + lk * (BK * 2);
        const char* bg = (const char*)g_yh
            + ((size_t)(lt & 31) * BN) * (DDIM * 2) + lk * (BK * 2);
        #pragma unroll
        for (int k = 0; k < 8; k++) {
            int i = tid + k * 256;
            int r = (i >> 3) & 127;
            int c = (i & 7) * 16;
            uint32_t off = swz((uint32_t)((i < 1024 ? r : BM + r) * 128 + c));
            const char* src = (i < 1024 ? ag : bg) + (size_t)r * (DDIM * 2) + c;
            CP_ASYNC16(sbase + off, src);
        }
        CP_COMMIT();
    };

    float acc[2][8][4];
    #pragma unroll
    for (int mt = 0; mt < 2; mt++)
        #pragma unroll
        for (int nt = 0; nt < 8; nt++)
            #pragma unroll
            for (int q = 0; q < 4; q++)
                acc[mt][nt][q] = 0.0f;

    int tile = blockIdx.x;
    // Continuous load stream state: next load = (lt, lk)
    int lt = tile, lk = 0;
    // Prologue: first 2 stages of first tile
    load_stage(0, lt, 0);
    load_stage(1, lt, 1);
    lk = 2;

    int sb = 0, lb = 2;
    while (tile < NTILES) {
        for (int it = 0; it < KITERS; ++it) {
            CP_WAIT1();            // stage for this iter resident
            __syncthreads();       // everyone done with buffer being refilled

            if (lt < NTILES) {
                load_stage(lb, lt, lk);
                if (++lk == KITERS) { lk = 0; lt += GRID_P; }
            } else {
                CP_COMMIT();       // keep group accounting uniform
            }

            const uint32_t sbase = smem_base + sb * STAGE_BYTES;
            #pragma unroll
            for (int ks = 0; ks < 4; ks++) {
                const uint32_t kb = ks * 32;
                uint32_t a[2][4];
                #pragma unroll
                for (int t = 0; t < 2; t++)
                    ldsm_x4(a[t], sbase + swz(a_rowoff[t] + kb + a_kb));
                uint32_t b[8][2];
                #pragma unroll
                for (int p = 0; p < 4; p++) {
                    uint32_t r[4];
                    ldsm_x4(r, sbase + swz(b_rowoff[p] + kb + b_kb));
                    b[2 * p][0] = r[0]; b[2 * p][1] = r[1];
                    b[2 * p + 1][0] = r[2]; b[2 * p + 1][1] = r[3];
                }
                #pragma unroll
                for (int mt = 0; mt < 2; mt++)
                    #pragma unroll
                    for (int nt = 0; nt < 8; nt++)
                        mma16816(acc[mt][nt], a[mt], b[nt]);
            }
            sb = (sb == NSTAGE - 1) ? 0 : sb + 1;
            lb = (lb == NSTAGE - 1) ? 0 : lb + 1;
        }

        // Epilogue for this tile (overlaps the in-flight loads of next tile)
        {
            const int rowA0 = (tile >> 5) * BM;
            const int rowB0 = (tile & 31) * BN;
            const int crow = rowA0 + wm * 32 + (lid >> 2);
            const int ccol = rowB0 + wn * 64 + (lid & 3) * 2;
            #pragma unroll
            for (int mt = 0; mt < 2; mt++) {
                #pragma unroll
                for (int nt = 0; nt < 8; nt++) {
                    float* p0 = C + (size_t)(crow + mt * 16) * NROWS + ccol + nt * 8;
                    float* p1 = p0 + 8 * NROWS;
                    *(float2*)p0 = make_float2(acc[mt][nt][0], acc[mt][nt][1]);
                    *(float2*)p1 = make_float2(acc[mt][nt][2], acc[mt][nt][3]);
                    acc[mt][nt][0] = 0.0f; acc[mt][nt][1] = 0.0f;
                    acc[mt][nt][2] = 0.0f; acc[mt][nt][3] = 0.0f;
                }
            }
        }
        tile += GRID_P;
    }
}

// ---------------------------------------------------------------------------
extern "C" void kernel_launch(void* const* d_in, const int* in_sizes, int n_in,
                              void* d_out, int out_size) {
    const float* x = (const float*)d_in[0];
    const float* y = (const float*)d_in[1];
    float* out = (float*)d_out;

    cudaFuncSetAttribute(gemm_kernel, cudaFuncAttributeMaxDynamicSharedMemorySize, SMEM_DYN);

    norm_kernel<<<2 * NROWS, 256>>>(x, y);
    gemm_kernel<<<GRID_P, 256, SMEM_DYN>>>(out);
}

// round 7
// speedup vs baseline: 1.2618x; 1.0213x over previous
#include <cuda_runtime.h>
#include <cuda_fp16.h>
#include <cstdint>

// CosSimilarity via fp16 mma.sync (legacy HMMA; tcgen05 unavailable: harness
// ptxas targets plain sm_103).
//  K1: normalize rows (x side pre-scaled by 1/TEMP=20) -> fp16 scratch.
//  K2: persistent HMMA GEMM (BM=BN=128, BK=64, 3 stages, 2 CTA/SM, warp 32x64)
//      with an mbarrier producer/consumer pipeline instead of __syncthreads:
//      full[s] tracks cp.async landing (count=256, noinc arrives);
//      empty[s] tracks per-warp consumption (count=8). Warps decouple; the
//      slowest warp no longer gates every K-iteration.

#define NROWS 4096
#define DDIM  1024
#define BM 128
#define BN 128
#define BK 64
#define NSTAGE 3
#define KITERS (DDIM / BK)              // 16
#define STAGE_BYTES ((BM + BN) * 128)   // 32 KB
#define SMEM_ST0 1024
#define SMEM_DYN (SMEM_ST0 + NSTAGE * STAGE_BYTES)
#define NTILES ((NROWS / BM) * (NROWS / BN))   // 1024
#define GRID_P 296                      // 2 x 148 SMs

__device__ __align__(1024) __half g_xh[NROWS * DDIM];
__device__ __align__(1024) __half g_yh[NROWS * DDIM];

__device__ __forceinline__ uint32_t smem_u32(const void* p) {
    uint32_t a;
    asm("{ .reg .u64 t; cvta.to.shared.u64 t, %1; cvt.u32.u64 %0, t; }" : "=r"(a) : "l"(p));
    return a;
}

#define CP_ASYNC16(dst, src) \
    asm volatile("cp.async.cg.shared.global [%0], [%1], 16;" :: "r"(dst), "l"(src))
#define CP_ASYNC_ARRIVE_NOINC(mbar) \
    asm volatile("cp.async.mbarrier.arrive.noinc.shared.b64 [%0];" :: "r"(mbar) : "memory")

#define MBAR_INIT(addr, cnt) \
    asm volatile("mbarrier.init.shared.b64 [%0], %1;" :: "r"(addr), "r"(cnt) : "memory")
#define MBAR_ARRIVE(addr) \
    asm volatile("mbarrier.arrive.shared.b64 _, [%0];" :: "r"(addr) : "memory")

#define MBAR_WAIT(addr, par) do {                                                  \
    uint32_t _m = (addr); uint32_t _p = (par); uint32_t _done;                     \
    asm volatile("{\n\t.reg .pred p;\n\t"                                          \
        "mbarrier.try_wait.parity.acquire.cta.shared::cta.b64 p, [%1], %2;\n\t"    \
        "selp.b32 %0, 1, 0, p;\n\t}"                                               \
        : "=r"(_done) : "r"(_m), "r"(_p) : "memory");                              \
    if (!_done) {                                                                  \
        asm volatile("{\n\t.reg .pred P1;\n\t"                                     \
            "WL_%=:\n\t"                                                           \
            "mbarrier.try_wait.parity.acquire.cta.shared::cta.b64 P1, [%0], %1, 0x989680;\n\t" \
            "@P1 bra.uni WD_%=;\n\t"                                               \
            "bra.uni WL_%=;\n\t"                                                   \
            "WD_%=:\n\t}" :: "r"(_m), "r"(_p) : "memory");                         \
    }                                                                              \
} while (0)

// Relaxed variant for producer empty-waits (post-wait accesses are cp.async only)
#define MBAR_WAIT_RLX(addr, par) do {                                              \
    uint32_t _m = (addr); uint32_t _p = (par); uint32_t _done;                     \
    asm volatile("{\n\t.reg .pred p;\n\t"                                          \
        "mbarrier.try_wait.parity.relaxed.cta.shared::cta.b64 p, [%1], %2, 0x989680;\n\t" \
        "selp.b32 %0, 1, 0, p;\n\t}"                                               \
        : "=r"(_done) : "r"(_m), "r"(_p) : "memory");                              \
    if (!_done) {                                                                  \
        asm volatile("{\n\t.reg .pred P1;\n\t"                                     \
            "WL_%=:\n\t"                                                           \
            "mbarrier.try_wait.parity.relaxed.cta.shared::cta.b64 P1, [%0], %1, 0x989680;\n\t" \
            "@P1 bra.uni WD_%=;\n\t"                                               \
            "bra.uni WL_%=;\n\t"                                                   \
            "WD_%=:\n\t}" :: "r"(_m), "r"(_p) : "memory");                         \
    }                                                                              \
} while (0)

__device__ __forceinline__ uint32_t swz(uint32_t off) {
    return off ^ ((off >> 3) & 0x70);
}

__device__ __forceinline__ void ldsm_x4(uint32_t* r, uint32_t addr) {
    asm volatile("ldmatrix.sync.aligned.m8n8.x4.shared.b16 {%0,%1,%2,%3}, [%4];"
                 : "=r"(r[0]), "=r"(r[1]), "=r"(r[2]), "=r"(r[3]) : "r"(addr));
}

__device__ __forceinline__ void mma16816(float* c, const uint32_t* a, const uint32_t* b) {
    asm volatile(
        "mma.sync.aligned.m16n8k16.row.col.f32.f16.f16.f32 "
        "{%0,%1,%2,%3}, {%4,%5,%6,%7}, {%8,%9}, {%0,%1,%2,%3};"
        : "+f"(c[0]), "+f"(c[1]), "+f"(c[2]), "+f"(c[3])
        : "r"(a[0]), "r"(a[1]), "r"(a[2]), "r"(a[3]), "r"(b[0]), "r"(b[1]));
}

// ---------------------------------------------------------------------------
// Kernel 1: row normalization -> fp16 (one 256-thread block per row)
// ---------------------------------------------------------------------------
__global__ void norm_kernel(const float* __restrict__ x, const float* __restrict__ y) {
    int row = blockIdx.x;
    const float4* src; __half2* dst; float extra;
    if (row < NROWS) {
        src = (const float4*)(x + (size_t)row * DDIM);
        dst = (__half2*)(g_xh + (size_t)row * DDIM);
        extra = 20.0f;                  // 1/TEMP folded into x side
    } else {
        int r = row - NROWS;
        src = (const float4*)(y + (size_t)r * DDIM);
        dst = (__half2*)(g_yh + (size_t)r * DDIM);
        extra = 1.0f;
    }
    int t = threadIdx.x;
    float4 v = src[t];
    float ss = v.x * v.x + v.y * v.y + v.z * v.z + v.w * v.w;
    #pragma unroll
    for (int o = 16; o > 0; o >>= 1) ss += __shfl_xor_sync(0xffffffffu, ss, o);

    __shared__ float wss[8];
    __shared__ float sinv;
    if ((t & 31) == 0) wss[t >> 5] = ss;
    __syncthreads();
    if (t == 0) {
        float tot = 0.0f;
        #pragma unroll
        for (int i = 0; i < 8; i++) tot += wss[i];
        sinv = extra / fmaxf(sqrtf(tot), 1e-8f);
    }
    __syncthreads();
    float inv = sinv;
    dst[2 * t]     = __floats2half2_rn(v.x * inv, v.y * inv);
    dst[2 * t + 1] = __floats2half2_rn(v.z * inv, v.w * inv);
}

// ---------------------------------------------------------------------------
// Kernel 2: persistent HMMA GEMM, mbarrier pipeline, 2 CTAs/SM
// ---------------------------------------------------------------------------
__global__ void __launch_bounds__(256, 2) gemm_kernel(float* __restrict__ C) {
    extern __shared__ __align__(1024) char smem[];
    const uint32_t smem_base = smem_u32(smem);
    const int tid = threadIdx.x;
    const int wid = tid >> 5;
    const int lid = tid & 31;

    const int wm = wid & 3;              // m band (32 rows each)
    const int wn = wid >> 2;             // n band (64 cols each)

    // barriers: full[s] @ base + s*8 ; empty[s] @ base + 24 + s*8
    if (tid == 0) {
        #pragma unroll
        for (int s = 0; s < NSTAGE; s++) {
            MBAR_INIT(smem_base + s * 8, 256);     // full: one noinc arrive/thread
            MBAR_INIT(smem_base + 24 + s * 8, 8);  // empty: one arrive/warp
        }
    }
    __syncthreads();

    // ldmatrix lane geometry
    const int g   = lid >> 3;
    const int rin = lid & 7;
    const int a_m  = (g & 1) * 8 + rin;
    const int a_kb = (g >> 1) * 16;
    const int b_n  = (g >> 1) * 8 + rin;
    const int b_kb = (g & 1) * 16;

    uint32_t a_rowoff[2], b_rowoff[4];
    #pragma unroll
    for (int t = 0; t < 2; t++)
        a_rowoff[t] = (uint32_t)(wm * 32 + t * 16 + a_m) * 128;
    #pragma unroll
    for (int p = 0; p < 4; p++)
        b_rowoff[p] = (uint32_t)(BM + wn * 64 + p * 16 + b_n) * 128;

    // Stage loader for (tile lt, k-slice lk): 8 cp.async/thread + noinc arrive.
    auto load_stage = [&](int sbuf, int lt, int lk) {
        uint32_t sbase = smem_base + SMEM_ST0 + sbuf * STAGE_BYTES;
        const char* ag = (const char*)g_xh
            + ((size_t)(lt >> 5) * BM) * (DDIM * 2) + lk * (BK * 2);
        const char* bg = (const char*)g_yh
            + ((size_t)(lt & 31) * BN) * (DDIM * 2) + lk * (BK * 2);
        #pragma unroll
        for (int k = 0; k < 8; k++) {
            int i = tid + k * 256;
            int r = (i >> 3) & 127;
            int c = (i & 7) * 16;
            uint32_t off = swz((uint32_t)((i < 1024 ? r : BM + r) * 128 + c));
            const char* src = (i < 1024 ? ag : bg) + (size_t)r * (DDIM * 2) + c;
            CP_ASYNC16(sbase + off, src);
        }
        CP_ASYNC_ARRIVE_NOINC(smem_base + sbuf * 8);
    };

    float acc[2][8][4];
    #pragma unroll
    for (int mt = 0; mt < 2; mt++)
        #pragma unroll
        for (int nt = 0; nt < 8; nt++)
            #pragma unroll
            for (int q = 0; q < 4; q++)
                acc[mt][nt][q] = 0.0f;

    int tile = blockIdx.x;
    int lt = tile, lk = 0;
    // Prologue: stages 0,1 of first tile (fresh empty barriers: no wait needed)
    load_stage(0, lt, 0);
    load_stage(1, lt, 1);
    lk = 2;

    int sb = 0, fpar = 0;     // consumer: buffer + full-parity
    int lb = 2, epar = 1;     // producer: buffer + empty-parity (first waits pass)
    while (tile < NTILES) {
        for (int it = 0; it < KITERS; ++it) {
            // Producer: refill next buffer (waits only on 3-ago consumption)
            if (lt < NTILES) {
                MBAR_WAIT_RLX(smem_base + 24 + lb * 8, epar);
                load_stage(lb, lt, lk);
                if (++lk == KITERS) { lk = 0; lt += GRID_P; }
                if (++lb == NSTAGE) { lb = 0; epar ^= 1; }
            }

            // Consumer: wait for this stage's data
            MBAR_WAIT(smem_base + sb * 8, fpar);

            const uint32_t sbase = smem_base + SMEM_ST0 + sb * STAGE_BYTES;
            #pragma unroll
            for (int ks = 0; ks < 4; ks++) {
                const uint32_t kb = ks * 32;
                uint32_t a[2][4];
                #pragma unroll
                for (int t = 0; t < 2; t++)
                    ldsm_x4(a[t], sbase + swz(a_rowoff[t] + kb + a_kb));
                uint32_t b[8][2];
                #pragma unroll
                for (int p = 0; p < 4; p++) {
                    uint32_t r[4];
                    ldsm_x4(r, sbase + swz(b_rowoff[p] + kb + b_kb));
                    b[2 * p][0] = r[0]; b[2 * p][1] = r[1];
                    b[2 * p + 1][0] = r[2]; b[2 * p + 1][1] = r[3];
                }
                #pragma unroll
                for (int mt = 0; mt < 2; mt++)
                    #pragma unroll
                    for (int nt = 0; nt < 8; nt++)
                        mma16816(acc[mt][nt], a[mt], b[nt]);
            }
            // This warp is done reading stage sb
            __syncwarp();
            if (lid == 0) MBAR_ARRIVE(smem_base + 24 + sb * 8);
            if (++sb == NSTAGE) { sb = 0; fpar ^= 1; }
        }

        // Epilogue for this tile (overlaps in-flight loads of next tile)
        {
            const int rowA0 = (tile >> 5) * BM;
            const int rowB0 = (tile & 31) * BN;
            const int crow = rowA0 + wm * 32 + (lid >> 2);
            const int ccol = rowB0 + wn * 64 + (lid & 3) * 2;
            #pragma unroll
            for (int mt = 0; mt < 2; mt++) {
                #pragma unroll
                for (int nt = 0; nt < 8; nt++) {
                    float* p0 = C + (size_t)(crow + mt * 16) * NROWS + ccol + nt * 8;
                    float* p1 = p0 + 8 * NROWS;
                    *(float2*)p0 = make_float2(acc[mt][nt][0], acc[mt][nt][1]);
                    *(float2*)p1 = make_float2(acc[mt][nt][2], acc[mt][nt][3]);
                    acc[mt][nt][0] = 0.0f; acc[mt][nt][1] = 0.0f;
                    acc[mt][nt][2] = 0.0f; acc[mt][nt][3] = 0.0f;
                }
            }
        }
        tile += GRID_P;
    }
}

// ---------------------------------------------------------------------------
extern "C" void kernel_launch(void* const* d_in, const int* in_sizes, int n_in,
                              void* d_out, int out_size) {
    const float* x = (const float*)d_in[0];
    const float* y = (const float*)d_in[1];
    float* out = (float*)d_out;

    cudaFuncSetAttribute(gemm_kernel, cudaFuncAttributeMaxDynamicSharedMemorySize, SMEM_DYN);

    norm_kernel<<<2 * NROWS, 256>>>(x, y);
    gemm_kernel<<<GRID_P, 256, SMEM_DYN>>>(out);
}

// round 8
// speedup vs baseline: 1.3193x; 1.0456x over previous
#include <cuda_runtime.h>
#include <cuda_fp16.h>
#include <cstdint>

// CosSimilarity via fp16 mma.sync (legacy HMMA; tcgen05 unavailable: harness
// ptxas targets plain sm_103).
//  K1: normalize rows (x side pre-scaled by 1/TEMP=20) -> fp16 scratch.
//  K2: persistent HMMA GEMM. BM=BN=128, BK=64, 3 stages, mbarrier pipeline.
//      NEW: 128-thread CTAs (4 warps, 2x2 grid of 64x64 warp tiles), 2 CTA/SM.
//      Regs cap 256/thread -> 128 accum regs fit; smem traffic/iter drops
//      128KB -> 96KB (A,B each read 2x instead of 2x/4x); smem floor ~12K
//      cyc/tile < tensor busy ~17.7K -> tensor-bound.

#define NROWS 4096
#define DDIM  1024
#define BM 128
#define BN 128
#define BK 64
#define NSTAGE 3
#define KITERS (DDIM / BK)              // 16
#define STAGE_BYTES ((BM + BN) * 128)   // 32 KB
#define SMEM_ST0 1024
#define SMEM_DYN (SMEM_ST0 + NSTAGE * STAGE_BYTES)
#define NTILES ((NROWS / BM) * (NROWS / BN))   // 1024
#define GRID_P 296                      // 2 x 148 SMs
#define NTHREADS 128

__device__ __align__(1024) __half g_xh[NROWS * DDIM];
__device__ __align__(1024) __half g_yh[NROWS * DDIM];

__device__ __forceinline__ uint32_t smem_u32(const void* p) {
    uint32_t a;
    asm("{ .reg .u64 t; cvta.to.shared.u64 t, %1; cvt.u32.u64 %0, t; }" : "=r"(a) : "l"(p));
    return a;
}

#define CP_ASYNC16(dst, src) \
    asm volatile("cp.async.cg.shared.global [%0], [%1], 16;" :: "r"(dst), "l"(src))
#define CP_ASYNC_ARRIVE_NOINC(mbar) \
    asm volatile("cp.async.mbarrier.arrive.noinc.shared.b64 [%0];" :: "r"(mbar) : "memory")

#define MBAR_INIT(addr, cnt) \
    asm volatile("mbarrier.init.shared.b64 [%0], %1;" :: "r"(addr), "r"(cnt) : "memory")
#define MBAR_ARRIVE(addr) \
    asm volatile("mbarrier.arrive.shared.b64 _, [%0];" :: "r"(addr) : "memory")

#define MBAR_WAIT(addr, par) do {                                                  \
    uint32_t _m = (addr); uint32_t _p = (par); uint32_t _done;                     \
    asm volatile("{\n\t.reg .pred p;\n\t"                                          \
        "mbarrier.try_wait.parity.acquire.cta.shared::cta.b64 p, [%1], %2;\n\t"    \
        "selp.b32 %0, 1, 0, p;\n\t}"                                               \
        : "=r"(_done) : "r"(_m), "r"(_p) : "memory");                              \
    if (!_done) {                                                                  \
        asm volatile("{\n\t.reg .pred P1;\n\t"                                     \
            "WL_%=:\n\t"                                                           \
            "mbarrier.try_wait.parity.acquire.cta.shared::cta.b64 P1, [%0], %1, 0x989680;\n\t" \
            "@P1 bra.uni WD_%=;\n\t"                                               \
            "bra.uni WL_%=;\n\t"                                                   \
            "WD_%=:\n\t}" :: "r"(_m), "r"(_p) : "memory");                         \
    }                                                                              \
} while (0)

// Relaxed variant for producer empty-waits (post-wait accesses are cp.async only)
#define MBAR_WAIT_RLX(addr, par) do {                                              \
    uint32_t _m = (addr); uint32_t _p = (par); uint32_t _done;                     \
    asm volatile("{\n\t.reg .pred p;\n\t"                                          \
        "mbarrier.try_wait.parity.relaxed.cta.shared::cta.b64 p, [%1], %2, 0x989680;\n\t" \
        "selp.b32 %0, 1, 0, p;\n\t}"                                               \
        : "=r"(_done) : "r"(_m), "r"(_p) : "memory");                              \
    if (!_done) {                                                                  \
        asm volatile("{\n\t.reg .pred P1;\n\t"                                     \
            "WL_%=:\n\t"                                                           \
            "mbarrier.try_wait.parity.relaxed.cta.shared::cta.b64 P1, [%0], %1, 0x989680;\n\t" \
            "@P1 bra.uni WD_%=;\n\t"                                               \
            "bra.uni WL_%=;\n\t"                                                   \
            "WD_%=:\n\t}" :: "r"(_m), "r"(_p) : "memory");                         \
    }                                                                              \
} while (0)

__device__ __forceinline__ uint32_t swz(uint32_t off) {
    return off ^ ((off >> 3) & 0x70);
}

__device__ __forceinline__ void ldsm_x4(uint32_t* r, uint32_t addr) {
    asm volatile("ldmatrix.sync.aligned.m8n8.x4.shared.b16 {%0,%1,%2,%3}, [%4];"
                 : "=r"(r[0]), "=r"(r[1]), "=r"(r[2]), "=r"(r[3]) : "r"(addr));
}

__device__ __forceinline__ void mma16816(float* c, const uint32_t* a, const uint32_t* b) {
    asm volatile(
        "mma.sync.aligned.m16n8k16.row.col.f32.f16.f16.f32 "
        "{%0,%1,%2,%3}, {%4,%5,%6,%7}, {%8,%9}, {%0,%1,%2,%3};"
        : "+f"(c[0]), "+f"(c[1]), "+f"(c[2]), "+f"(c[3])
        : "r"(a[0]), "r"(a[1]), "r"(a[2]), "r"(a[3]), "r"(b[0]), "r"(b[1]));
}

// ---------------------------------------------------------------------------
// Kernel 1: row normalization -> fp16 (one 256-thread block per row)
// ---------------------------------------------------------------------------
__global__ void norm_kernel(const float* __restrict__ x, const float* __restrict__ y) {
    int row = blockIdx.x;
    const float4* src; __half2* dst; float extra;
    if (row < NROWS) {
        src = (const float4*)(x + (size_t)row * DDIM);
        dst = (__half2*)(g_xh + (size_t)row * DDIM);
        extra = 20.0f;                  // 1/TEMP folded into x side
    } else {
        int r = row - NROWS;
        src = (const float4*)(y + (size_t)r * DDIM);
        dst = (__half2*)(g_yh + (size_t)r * DDIM);
        extra = 1.0f;
    }
    int t = threadIdx.x;
    float4 v = src[t];
    float ss = v.x * v.x + v.y * v.y + v.z * v.z + v.w * v.w;
    #pragma unroll
    for (int o = 16; o > 0; o >>= 1) ss += __shfl_xor_sync(0xffffffffu, ss, o);

    __shared__ float wss[8];
    __shared__ float sinv;
    if ((t & 31) == 0) wss[t >> 5] = ss;
    __syncthreads();
    if (t == 0) {
        float tot = 0.0f;
        #pragma unroll
        for (int i = 0; i < 8; i++) tot += wss[i];
        sinv = extra / fmaxf(sqrtf(tot), 1e-8f);
    }
    __syncthreads();
    float inv = sinv;
    dst[2 * t]     = __floats2half2_rn(v.x * inv, v.y * inv);
    dst[2 * t + 1] = __floats2half2_rn(v.z * inv, v.w * inv);
}

// ---------------------------------------------------------------------------
// Kernel 2: persistent HMMA GEMM, 4 warps/CTA, warp tile 64x64, 2 CTA/SM
// ---------------------------------------------------------------------------
__global__ void __launch_bounds__(NTHREADS, 2) gemm_kernel(float* __restrict__ C) {
    extern __shared__ __align__(1024) char smem[];
    const uint32_t smem_base = smem_u32(smem);
    const int tid = threadIdx.x;
    const int wid = tid >> 5;
    const int lid = tid & 31;

    const int wm = wid & 1;              // m band (64 rows each)
    const int wn = wid >> 1;             // n band (64 cols each)

    // barriers: full[s] @ base + s*8 ; empty[s] @ base + 24 + s*8
    if (tid == 0) {
        #pragma unroll
        for (int s = 0; s < NSTAGE; s++) {
            MBAR_INIT(smem_base + s * 8, NTHREADS); // full: one noinc arrive/thread
            MBAR_INIT(smem_base + 24 + s * 8, 4);   // empty: one arrive/warp
        }
    }
    __syncthreads();

    // ldmatrix lane geometry
    const int g   = lid >> 3;
    const int rin = lid & 7;
    const int a_m  = (g & 1) * 8 + rin;
    const int a_kb = (g >> 1) * 16;
    const int b_n  = (g >> 1) * 8 + rin;
    const int b_kb = (g & 1) * 16;

    uint32_t a_rowoff[4], b_rowoff[4];
    #pragma unroll
    for (int t = 0; t < 4; t++)
        a_rowoff[t] = (uint32_t)(wm * 64 + t * 16 + a_m) * 128;
    #pragma unroll
    for (int p = 0; p < 4; p++)
        b_rowoff[p] = (uint32_t)(BM + wn * 64 + p * 16 + b_n) * 128;

    // Stage loader for (tile lt, k-slice lk): 2048 chunks / 128 thr = 16 each.
    auto load_stage = [&](int sbuf, int lt, int lk) {
        uint32_t sbase = smem_base + SMEM_ST0 + sbuf * STAGE_BYTES;
        const char* ag = (const char*)g_xh
            + ((size_t)(lt >> 5) * BM) * (DDIM * 2) + lk * (BK * 2);
        const char* bg = (const char*)g_yh
            + ((size_t)(lt & 31) * BN) * (DDIM * 2) + lk * (BK * 2);
        #pragma unroll
        for (int k = 0; k < 16; k++) {
            int i = tid + k * NTHREADS;
            int r = (i >> 3) & 127;
            int c = (i & 7) * 16;
            uint32_t off = swz((uint32_t)((i < 1024 ? r : BM + r) * 128 + c));
            const char* src = (i < 1024 ? ag : bg) + (size_t)r * (DDIM * 2) + c;
            CP_ASYNC16(sbase + off, src);
        }
        CP_ASYNC_ARRIVE_NOINC(smem_base + sbuf * 8);
    };

    float acc[4][8][4];
    #pragma unroll
    for (int mt = 0; mt < 4; mt++)
        #pragma unroll
        for (int nt = 0; nt < 8; nt++)
            #pragma unroll
            for (int q = 0; q < 4; q++)
                acc[mt][nt][q] = 0.0f;

    int tile = blockIdx.x;
    int lt = tile, lk = 0;
    // Prologue: stages 0,1 of first tile (fresh empty barriers: no wait needed)
    load_stage(0, lt, 0);
    load_stage(1, lt, 1);
    lk = 2;

    int sb = 0, fpar = 0;     // consumer: buffer + full-parity
    int lb = 2, epar = 1;     // producer: buffer + empty-parity (first waits pass)
    while (tile < NTILES) {
        for (int it = 0; it < KITERS; ++it) {
            // Producer: refill next buffer (waits only on 3-ago consumption)
            if (lt < NTILES) {
                MBAR_WAIT_RLX(smem_base + 24 + lb * 8, epar);
                load_stage(lb, lt, lk);
                if (++lk == KITERS) { lk = 0; lt += GRID_P; }
                if (++lb == NSTAGE) { lb = 0; epar ^= 1; }
            }

            // Consumer: wait for this stage's data
            MBAR_WAIT(smem_base + sb * 8, fpar);

            const uint32_t sbase = smem_base + SMEM_ST0 + sb * STAGE_BYTES;
            #pragma unroll
            for (int ks = 0; ks < 4; ks++) {
                const uint32_t kb = ks * 32;
                uint32_t a[4][4];
                #pragma unroll
                for (int t = 0; t < 4; t++)
                    ldsm_x4(a[t], sbase + swz(a_rowoff[t] + kb + a_kb));
                uint32_t b[8][2];
                #pragma unroll
                for (int p = 0; p < 4; p++) {
                    uint32_t r[4];
                    ldsm_x4(r, sbase + swz(b_rowoff[p] + kb + b_kb));
                    b[2 * p][0] = r[0]; b[2 * p][1] = r[1];
                    b[2 * p + 1][0] = r[2]; b[2 * p + 1][1] = r[3];
                }
                #pragma unroll
                for (int mt = 0; mt < 4; mt++)
                    #pragma unroll
                    for (int nt = 0; nt < 8; nt++)
                        mma16816(acc[mt][nt], a[mt], b[nt]);
            }
            // This warp is done reading stage sb
            __syncwarp();
            if (lid == 0) MBAR_ARRIVE(smem_base + 24 + sb * 8);
            if (++sb == NSTAGE) { sb = 0; fpar ^= 1; }
        }

        // Epilogue for this tile (overlaps in-flight loads of next tile)
        {
            const int rowA0 = (tile >> 5) * BM;
            const int rowB0 = (tile & 31) * BN;
            const int crow = rowA0 + wm * 64 + (lid >> 2);
            const int ccol = rowB0 + wn * 64 + (lid & 3) * 2;
            #pragma unroll
            for (int mt = 0; mt < 4; mt++) {
                #pragma unroll
                for (int nt = 0; nt < 8; nt++) {
                    float* p0 = C + (size_t)(crow + mt * 16) * NROWS + ccol + nt * 8;
                    float* p1 = p0 + 8 * NROWS;
                    *(float2*)p0 = make_float2(acc[mt][nt][0], acc[mt][nt][1]);
                    *(float2*)p1 = make_float2(acc[mt][nt][2], acc[mt][nt][3]);
                    acc[mt][nt][0] = 0.0f; acc[mt][nt][1] = 0.0f;
                    acc[mt][nt][2] = 0.0f; acc[mt][nt][3] = 0.0f;
                }
            }
        }
        tile += GRID_P;
    }
}

// ---------------------------------------------------------------------------
extern "C" void kernel_launch(void* const* d_in, const int* in_sizes, int n_in,
                              void* d_out, int out_size) {
    const float* x = (const float*)d_in[0];
    const float* y = (const float*)d_in[1];
    float* out = (float*)d_out;

    cudaFuncSetAttribute(gemm_kernel, cudaFuncAttributeMaxDynamicSharedMemorySize, SMEM_DYN);

    norm_kernel<<<2 * NROWS, 256>>>(x, y);
    gemm_kernel<<<GRID_P, NTHREADS, SMEM_DYN>>>(out);
}